// round 3
// baseline (speedup 1.0000x reference)
#include <cuda_runtime.h>
#include <math.h>

#define EPS 1e-12f
constexpr int K      = 8;
constexpr int MAXE   = 3200000;   // 2 * E_UND
constexpr int MAXN   = 100000;
constexpr int ITERS  = 5;         // fixed by problem setup

// Scratch (allocation-free rule: __device__ globals)
// pair-interleaved messages: pair p -> 16 floats = [m_e(8) | m_rev(8)], 64B block
__device__ float g_pair[(size_t)(MAXE / 2) * 2 * K];
__device__ float g_inlog[2][(size_t)MAXN * K];
__device__ float g_pp[(size_t)MAXN * K];           // prior * exp(in_log)
__device__ float g_psi[K * K];

__device__ __forceinline__ void red_add_v4(float* p, float a, float b, float c, float d) {
    asm volatile("red.global.add.v4.f32 [%0], {%1,%2,%3,%4};"
                 :: "l"(p), "f"(a), "f"(b), "f"(c), "f"(d) : "memory");
}

__global__ void k_psi(const float* __restrict__ pot) {
    int i = threadIdx.x;
    if (i < K * K) g_psi[i] = expf(pot[i]);
}

__global__ void k_zero4(float* __restrict__ p, int n4) {
    int i = blockIdx.x * blockDim.x + threadIdx.x;
    if (i < n4) reinterpret_cast<float4*>(p)[i] = make_float4(0.f, 0.f, 0.f, 0.f);
}

// Initial scatter, fully coalesced: inlog[dst[e]] += log(max(msgs[e],EPS)) over ALL E edges.
__global__ void k_scatter(const float* __restrict__ msgs, const int* __restrict__ dst,
                          float* __restrict__ inlog, int E) {
    int e = blockIdx.x * blockDim.x + threadIdx.x;
    if (e >= E) return;
    const float4* m4 = reinterpret_cast<const float4*>(msgs + (size_t)e * K);
    float4 a = m4[0], b = m4[1];
    float* d = inlog + (size_t)dst[e] * K;
    red_add_v4(d,     __logf(fmaxf(a.x, EPS)), __logf(fmaxf(a.y, EPS)),
                      __logf(fmaxf(a.z, EPS)), __logf(fmaxf(a.w, EPS)));
    red_add_v4(d + 4, __logf(fmaxf(b.x, EPS)), __logf(fmaxf(b.y, EPS)),
                      __logf(fmaxf(b.z, EPS)), __logf(fmaxf(b.w, EPS)));
}

// Per-node: pp = prior * exp(in_log_cur); zero in_log_next.
__global__ void k_pp_zero(const float* __restrict__ inlog_cur, const float* __restrict__ prior,
                          float* __restrict__ pp, float* __restrict__ inlog_next_zero, int n4) {
    int i = blockIdx.x * blockDim.x + threadIdx.x;
    if (i >= n4) return;
    float4 v = reinterpret_cast<const float4*>(inlog_cur)[i];
    float4 p = reinterpret_cast<const float4*>(prior)[i];
    float4 o;
    o.x = p.x * __expf(v.x); o.y = p.y * __expf(v.y);
    o.z = p.z * __expf(v.z); o.w = p.w * __expf(v.w);
    reinterpret_cast<float4*>(pp)[i] = o;
    reinterpret_cast<float4*>(inlog_next_zero)[i] = make_float4(0.f, 0.f, 0.f, 0.f);
}

// Shared math: given old pair messages (ma = m[e], mb = m[rev]) and node products,
// produce new pair messages + scatter their logs. Templated on nothing; inlined.
__device__ __forceinline__ void pair_math(
    const float* __restrict__ sp,
    float4 ma0, float4 ma1, float4 mb0, float4 mb1,
    float4 pa0, float4 pa1, float4 pb0, float4 pb1,
    int s1, int s2,
    float4& w0, float4& w1, float4& w2, float4& w3,
    float* __restrict__ inlog_nxt)
{
    float t1[K], t2[K];
    t1[0] = fmaxf(__fdividef(pa0.x, fmaxf(mb0.x, EPS)), EPS);
    t1[1] = fmaxf(__fdividef(pa0.y, fmaxf(mb0.y, EPS)), EPS);
    t1[2] = fmaxf(__fdividef(pa0.z, fmaxf(mb0.z, EPS)), EPS);
    t1[3] = fmaxf(__fdividef(pa0.w, fmaxf(mb0.w, EPS)), EPS);
    t1[4] = fmaxf(__fdividef(pa1.x, fmaxf(mb1.x, EPS)), EPS);
    t1[5] = fmaxf(__fdividef(pa1.y, fmaxf(mb1.y, EPS)), EPS);
    t1[6] = fmaxf(__fdividef(pa1.z, fmaxf(mb1.z, EPS)), EPS);
    t1[7] = fmaxf(__fdividef(pa1.w, fmaxf(mb1.w, EPS)), EPS);

    t2[0] = fmaxf(__fdividef(pb0.x, fmaxf(ma0.x, EPS)), EPS);
    t2[1] = fmaxf(__fdividef(pb0.y, fmaxf(ma0.y, EPS)), EPS);
    t2[2] = fmaxf(__fdividef(pb0.z, fmaxf(ma0.z, EPS)), EPS);
    t2[3] = fmaxf(__fdividef(pb0.w, fmaxf(ma0.w, EPS)), EPS);
    t2[4] = fmaxf(__fdividef(pb1.x, fmaxf(ma1.x, EPS)), EPS);
    t2[5] = fmaxf(__fdividef(pb1.y, fmaxf(ma1.y, EPS)), EPS);
    t2[6] = fmaxf(__fdividef(pb1.z, fmaxf(ma1.z, EPS)), EPS);
    t2[7] = fmaxf(__fdividef(pb1.w, fmaxf(ma1.w, EPS)), EPS);

    float m1[K], m2[K];
#pragma unroll
    for (int k = 0; k < K; k++) { m1[k] = t1[0] * sp[k]; m2[k] = t2[0] * sp[k]; }
#pragma unroll
    for (int j = 1; j < K; j++) {
#pragma unroll
        for (int k = 0; k < K; k++) {
            m1[k] = fmaf(t1[j], sp[j * K + k], m1[k]);
            m2[k] = fmaf(t2[j], sp[j * K + k], m2[k]);
        }
    }

    float s1s = (m1[0] + m1[1]) + (m1[2] + m1[3]) + ((m1[4] + m1[5]) + (m1[6] + m1[7]));
    float s2s = (m2[0] + m2[1]) + (m2[2] + m2[3]) + ((m2[4] + m2[5]) + (m2[6] + m2[7]));
    float i1 = __fdividef(1.0f, fmaxf(s1s, EPS));
    float i2 = __fdividef(1.0f, fmaxf(s2s, EPS));

    float o1[K], o2[K];
#pragma unroll
    for (int k = 0; k < K; k++) { o1[k] = m1[k] * i1; o2[k] = m2[k] * i2; }

    w0 = make_float4(o1[0], o1[1], o1[2], o1[3]);
    w1 = make_float4(o1[4], o1[5], o1[6], o1[7]);
    w2 = make_float4(o2[0], o2[1], o2[2], o2[3]);
    w3 = make_float4(o2[4], o2[5], o2[6], o2[7]);

    float l1[K], l2[K];
#pragma unroll
    for (int k = 0; k < K; k++) {
        l1[k] = __logf(o1[k] > EPS ? o1[k] : EPS);
        l2[k] = __logf(o2[k] > EPS ? o2[k] : EPS);
    }
    // new m[e] flows to dst(e)=s2; new m[rev] flows to dst(rev)=s1
    float* d2 = inlog_nxt + (size_t)s2 * K;
    red_add_v4(d2,     l1[0], l1[1], l1[2], l1[3]);
    red_add_v4(d2 + 4, l1[4], l1[5], l1[6], l1[7]);
    float* d1 = inlog_nxt + (size_t)s1 * K;
    red_add_v4(d1,     l2[0], l2[1], l2[2], l2[3]);
    red_add_v4(d1 + 4, l2[4], l2[5], l2[6], l2[7]);
}

// Iteration 0: read ORIGINAL message layout (random gather at rev[e]),
// write pair-interleaved buffer. Pair p corresponds to edge e=p (p < E2).
__global__ void k_update_first(const float* __restrict__ msgs, float* __restrict__ pairbuf,
                               const float* __restrict__ pp, const int* __restrict__ src,
                               const int* __restrict__ dst, const int* __restrict__ rev,
                               float* __restrict__ inlog_nxt, int E2) {
    __shared__ float sp[K * K];
    if (threadIdx.x < K * K) sp[threadIdx.x] = g_psi[threadIdx.x];
    __syncthreads();

    int p = blockIdx.x * blockDim.x + threadIdx.x;
    if (p >= E2) return;
    int r  = rev[p];
    int s1 = src[p];
    int s2 = dst[p];

    const float4* m4a = reinterpret_cast<const float4*>(msgs + (size_t)p * K);
    const float4* m4b = reinterpret_cast<const float4*>(msgs + (size_t)r * K);
    float4 ma0 = m4a[0], ma1 = m4a[1], mb0 = m4b[0], mb1 = m4b[1];
    const float4* p14 = reinterpret_cast<const float4*>(pp + (size_t)s1 * K);
    const float4* p24 = reinterpret_cast<const float4*>(pp + (size_t)s2 * K);

    float4 w0, w1, w2, w3;
    pair_math(sp, ma0, ma1, mb0, mb1, p14[0], p14[1], p24[0], p24[1],
              s1, s2, w0, w1, w2, w3, inlog_nxt);

    float4* out4 = reinterpret_cast<float4*>(pairbuf + (size_t)p * 2 * K);
    out4[0] = w0; out4[1] = w1; out4[2] = w2; out4[3] = w3;
}

// Iterations 1..: fully coalesced in-place pair update.
__global__ void k_update_pair(float* __restrict__ pairbuf,
                              const float* __restrict__ pp, const int* __restrict__ src,
                              const int* __restrict__ dst,
                              float* __restrict__ inlog_nxt, int E2) {
    __shared__ float sp[K * K];
    if (threadIdx.x < K * K) sp[threadIdx.x] = g_psi[threadIdx.x];
    __syncthreads();

    int p = blockIdx.x * blockDim.x + threadIdx.x;
    if (p >= E2) return;
    int s1 = src[p];
    int s2 = dst[p];

    float4* blk = reinterpret_cast<float4*>(pairbuf + (size_t)p * 2 * K);
    float4 ma0 = blk[0], ma1 = blk[1], mb0 = blk[2], mb1 = blk[3];
    const float4* p14 = reinterpret_cast<const float4*>(pp + (size_t)s1 * K);
    const float4* p24 = reinterpret_cast<const float4*>(pp + (size_t)s2 * K);

    float4 w0, w1, w2, w3;
    pair_math(sp, ma0, ma1, mb0, mb1, p14[0], p14[1], p24[0], p24[1],
              s1, s2, w0, w1, w2, w3, inlog_nxt);

    blk[0] = w0; blk[1] = w1; blk[2] = w2; blk[3] = w3;
}

// Beliefs: out = normalize( max(prior * exp(in_log), EPS) )
__global__ void k_belief(const float* __restrict__ inlog, const float* __restrict__ prior,
                         float* __restrict__ out, int N) {
    int i = blockIdx.x * blockDim.x + threadIdx.x;
    if (i >= N) return;
    const float4* l4 = reinterpret_cast<const float4*>(inlog + (size_t)i * K);
    const float4* p4 = reinterpret_cast<const float4*>(prior + (size_t)i * K);
    float4 la = l4[0], lb = l4[1];
    float4 pa = p4[0], pb = p4[1];
    float b[K];
    b[0] = fmaxf(pa.x * __expf(la.x), EPS);
    b[1] = fmaxf(pa.y * __expf(la.y), EPS);
    b[2] = fmaxf(pa.z * __expf(la.z), EPS);
    b[3] = fmaxf(pa.w * __expf(la.w), EPS);
    b[4] = fmaxf(pb.x * __expf(lb.x), EPS);
    b[5] = fmaxf(pb.y * __expf(lb.y), EPS);
    b[6] = fmaxf(pb.z * __expf(lb.z), EPS);
    b[7] = fmaxf(pb.w * __expf(lb.w), EPS);
    float s = (b[0] + b[1]) + (b[2] + b[3]) + ((b[4] + b[5]) + (b[6] + b[7]));
    float inv = __fdividef(1.0f, fmaxf(s, EPS));
    float4* o4 = reinterpret_cast<float4*>(out + (size_t)i * K);
    o4[0] = make_float4(b[0] * inv, b[1] * inv, b[2] * inv, b[3] * inv);
    o4[1] = make_float4(b[4] * inv, b[5] * inv, b[6] * inv, b[7] * inv);
}

extern "C" void kernel_launch(void* const* d_in, const int* in_sizes, int n_in,
                              void* d_out, int out_size) {
    const float* prior     = (const float*)d_in[0];
    const float* messages  = (const float*)d_in[1];
    const float* potential = (const float*)d_in[2];
    const int*   src       = (const int*)d_in[3];
    const int*   dst       = (const int*)d_in[4];
    const int*   rev       = (const int*)d_in[5];
    // d_in[6] = iterations (fixed 5 by problem setup)

    int E  = in_sizes[3];
    int E2 = E / 2;
    int N  = in_sizes[0] / K;
    float* out = (float*)d_out;

    float *pairbuf, *inlogBase, *pp;
    cudaGetSymbolAddress((void**)&pairbuf, g_pair);
    cudaGetSymbolAddress((void**)&inlogBase, g_inlog);
    cudaGetSymbolAddress((void**)&pp, g_pp);
    float* inlog[2] = { inlogBase, inlogBase + (size_t)MAXN * K };

    const int TB = 256;
    int gE  = (E + TB - 1) / TB;
    int gE2 = (E2 + TB - 1) / TB;
    int n4  = (N * K) / 4;
    int gN4 = (n4 + TB - 1) / TB;
    int gN  = (N + TB - 1) / TB;

    k_psi<<<1, 64>>>(potential);
    k_zero4<<<gN4, TB>>>(inlog[0], n4);
    k_scatter<<<gE, TB>>>(messages, dst, inlog[0], E);

    for (int it = 0; it < ITERS; it++) {
        k_pp_zero<<<gN4, TB>>>(inlog[it & 1], prior, pp, inlog[(it + 1) & 1], n4);
        if (it == 0) {
            k_update_first<<<gE2, TB>>>(messages, pairbuf, pp, src, dst, rev,
                                        inlog[1], E2);
        } else {
            k_update_pair<<<gE2, TB>>>(pairbuf, pp, src, dst,
                                       inlog[(it + 1) & 1], E2);
        }
    }

    k_belief<<<gN, TB>>>(inlog[ITERS & 1], prior, out, N);
}

// round 4
// speedup vs baseline: 1.1630x; 1.1630x over previous
#include <cuda_runtime.h>
#include <math.h>

#define EPS 1e-12f
constexpr int K      = 8;
constexpr int MAXE   = 3200000;   // 2 * E_UND
constexpr int MAXN   = 100000;
constexpr int ITERS  = 5;         // fixed by problem setup

// Scratch (allocation-free rule: __device__ globals)
__device__ float g_msg[(size_t)MAXE * K];          // single in-place message buffer
__device__ float g_inlog[2][(size_t)MAXN * K];
__device__ float g_pp[(size_t)MAXN * K];           // prior * exp(in_log)
__device__ float g_psi[K * K];

__device__ __forceinline__ void red_add_v4(float* p, float a, float b, float c, float d) {
    asm volatile("red.global.add.v4.f32 [%0], {%1,%2,%3,%4};"
                 :: "l"(p), "f"(a), "f"(b), "f"(c), "f"(d) : "memory");
}

// Launch 0: zero inlog[0] AND compute psi = exp(potential) (block 0 only).
__global__ void k_zero_psi(float* __restrict__ p, int n4, const float* __restrict__ pot) {
    if (blockIdx.x == 0 && threadIdx.x < K * K) g_psi[threadIdx.x] = expf(pot[threadIdx.x]);
    int i = blockIdx.x * blockDim.x + threadIdx.x;
    if (i < n4) reinterpret_cast<float4*>(p)[i] = make_float4(0.f, 0.f, 0.f, 0.f);
}

// Launch 1: initial scatter, coalesced over all E edges.
__global__ void k_scatter(const float* __restrict__ msgs, const int* __restrict__ dst,
                          float* __restrict__ inlog, int E) {
    int e = blockIdx.x * blockDim.x + threadIdx.x;
    if (e >= E) return;
    const float4* m4 = reinterpret_cast<const float4*>(msgs + (size_t)e * K);
    float4 a = m4[0], b = m4[1];
    float* d = inlog + (size_t)dst[e] * K;
    red_add_v4(d,     __logf(fmaxf(a.x, EPS)), __logf(fmaxf(a.y, EPS)),
                      __logf(fmaxf(a.z, EPS)), __logf(fmaxf(a.w, EPS)));
    red_add_v4(d + 4, __logf(fmaxf(b.x, EPS)), __logf(fmaxf(b.y, EPS)),
                      __logf(fmaxf(b.z, EPS)), __logf(fmaxf(b.w, EPS)));
}

// Per-node: pp = prior * exp(in_log_cur); zero in_log_next.
__global__ void k_pp_zero(const float* __restrict__ inlog_cur, const float* __restrict__ prior,
                          float* __restrict__ pp, float* __restrict__ inlog_next_zero, int n4) {
    int i = blockIdx.x * blockDim.x + threadIdx.x;
    if (i >= n4) return;
    float4 v = reinterpret_cast<const float4*>(inlog_cur)[i];
    float4 p = reinterpret_cast<const float4*>(prior)[i];
    float4 o;
    o.x = p.x * __expf(v.x); o.y = p.y * __expf(v.y);
    o.z = p.z * __expf(v.z); o.w = p.w * __expf(v.w);
    reinterpret_cast<float4*>(pp)[i] = o;
    reinterpret_cast<float4*>(inlog_next_zero)[i] = make_float4(0.f, 0.f, 0.f, 0.f);
}

// One direction of the pair update, fully sequential to minimize live registers:
// t = max(pp_src / max(m_partner_old, EPS), EPS);  m_new = normalize(t @ psi);
// write m_new at edge slot; scatter log(m_new) into inlog_nxt[dest].
__device__ __forceinline__ void one_dir(
    const float* __restrict__ sp,
    float4 mb0, float4 mb1,                 // partner's OLD message (divisor)
    const float* __restrict__ pp_src,       // pp row of this direction's source
    float* __restrict__ out_slot,           // where new message goes
    float* __restrict__ inlog_dest)         // inlog row of this direction's dest
{
    const float4* p4 = reinterpret_cast<const float4*>(pp_src);
    float4 pa0 = p4[0], pa1 = p4[1];

    float t[K];
    t[0] = fmaxf(__fdividef(pa0.x, fmaxf(mb0.x, EPS)), EPS);
    t[1] = fmaxf(__fdividef(pa0.y, fmaxf(mb0.y, EPS)), EPS);
    t[2] = fmaxf(__fdividef(pa0.z, fmaxf(mb0.z, EPS)), EPS);
    t[3] = fmaxf(__fdividef(pa0.w, fmaxf(mb0.w, EPS)), EPS);
    t[4] = fmaxf(__fdividef(pa1.x, fmaxf(mb1.x, EPS)), EPS);
    t[5] = fmaxf(__fdividef(pa1.y, fmaxf(mb1.y, EPS)), EPS);
    t[6] = fmaxf(__fdividef(pa1.z, fmaxf(mb1.z, EPS)), EPS);
    t[7] = fmaxf(__fdividef(pa1.w, fmaxf(mb1.w, EPS)), EPS);

    float m[K];
#pragma unroll
    for (int k = 0; k < K; k++) m[k] = t[0] * sp[k];
#pragma unroll
    for (int j = 1; j < K; j++) {
#pragma unroll
        for (int k = 0; k < K; k++) m[k] = fmaf(t[j], sp[j * K + k], m[k]);
    }

    float s = (m[0] + m[1]) + (m[2] + m[3]) + ((m[4] + m[5]) + (m[6] + m[7]));
    float inv = __fdividef(1.0f, fmaxf(s, EPS));
#pragma unroll
    for (int k = 0; k < K; k++) m[k] = m[k] * inv;

    float4* w = reinterpret_cast<float4*>(out_slot);
    w[0] = make_float4(m[0], m[1], m[2], m[3]);
    w[1] = make_float4(m[4], m[5], m[6], m[7]);

    float l[K];
#pragma unroll
    for (int k = 0; k < K; k++) l[k] = __logf(m[k] > EPS ? m[k] : EPS);
    red_add_v4(inlog_dest,     l[0], l[1], l[2], l[3]);
    red_add_v4(inlog_dest + 4, l[4], l[5], l[6], l[7]);
}

// Pair update, in-place: thread p handles edges p and r=rev[p].
__global__ void __launch_bounds__(256)
k_update(const float* __restrict__ cur, float* __restrict__ out,
         const float* __restrict__ pp, const int* __restrict__ src,
         const int* __restrict__ dst, const int* __restrict__ rev,
         float* __restrict__ inlog_nxt, int E2) {
    __shared__ float sp[K * K];
    if (threadIdx.x < K * K) sp[threadIdx.x] = g_psi[threadIdx.x];
    __syncthreads();

    int p = blockIdx.x * blockDim.x + threadIdx.x;
    if (p >= E2) return;

    int r  = rev[p];              // coalesced in practice (r = p + E_UND)
    int s1 = src[p];
    int s2 = dst[p];              // dst[p] == src[r]

    // Load both old messages first (both needed as divisors; in-place safety).
    const float4* m4a = reinterpret_cast<const float4*>(cur + (size_t)p * K);
    const float4* m4b = reinterpret_cast<const float4*>(cur + (size_t)r * K);
    float4 ma0 = m4a[0], ma1 = m4a[1];     // old m[p]
    float4 mb0 = m4b[0], mb1 = m4b[1];     // old m[r]

    // Direction p: src=s1, dst=s2, divisor = old m[r].
    one_dir(sp, mb0, mb1, pp + (size_t)s1 * K, out + (size_t)p * K,
            inlog_nxt + (size_t)s2 * K);
    // Direction r: src=s2, dst=s1, divisor = old m[p].
    one_dir(sp, ma0, ma1, pp + (size_t)s2 * K, out + (size_t)r * K,
            inlog_nxt + (size_t)s1 * K);
}

// Beliefs: out = normalize( max(prior * exp(in_log), EPS) )
__global__ void k_belief(const float* __restrict__ inlog, const float* __restrict__ prior,
                         float* __restrict__ out, int N) {
    int i = blockIdx.x * blockDim.x + threadIdx.x;
    if (i >= N) return;
    const float4* l4 = reinterpret_cast<const float4*>(inlog + (size_t)i * K);
    const float4* p4 = reinterpret_cast<const float4*>(prior + (size_t)i * K);
    float4 la = l4[0], lb = l4[1];
    float4 pa = p4[0], pb = p4[1];
    float b[K];
    b[0] = fmaxf(pa.x * __expf(la.x), EPS);
    b[1] = fmaxf(pa.y * __expf(la.y), EPS);
    b[2] = fmaxf(pa.z * __expf(la.z), EPS);
    b[3] = fmaxf(pa.w * __expf(la.w), EPS);
    b[4] = fmaxf(pb.x * __expf(lb.x), EPS);
    b[5] = fmaxf(pb.y * __expf(lb.y), EPS);
    b[6] = fmaxf(pb.z * __expf(lb.z), EPS);
    b[7] = fmaxf(pb.w * __expf(lb.w), EPS);
    float s = (b[0] + b[1]) + (b[2] + b[3]) + ((b[4] + b[5]) + (b[6] + b[7]));
    float inv = __fdividef(1.0f, fmaxf(s, EPS));
    float4* o4 = reinterpret_cast<float4*>(out + (size_t)i * K);
    o4[0] = make_float4(b[0] * inv, b[1] * inv, b[2] * inv, b[3] * inv);
    o4[1] = make_float4(b[4] * inv, b[5] * inv, b[6] * inv, b[7] * inv);
}

extern "C" void kernel_launch(void* const* d_in, const int* in_sizes, int n_in,
                              void* d_out, int out_size) {
    const float* prior     = (const float*)d_in[0];
    const float* messages  = (const float*)d_in[1];
    const float* potential = (const float*)d_in[2];
    const int*   src       = (const int*)d_in[3];
    const int*   dst       = (const int*)d_in[4];
    const int*   rev       = (const int*)d_in[5];
    // d_in[6] = iterations (fixed 5 by problem setup)

    int E  = in_sizes[3];
    int E2 = E / 2;
    int N  = in_sizes[0] / K;
    float* out = (float*)d_out;

    float *msg, *inlogBase, *pp;
    cudaGetSymbolAddress((void**)&msg, g_msg);
    cudaGetSymbolAddress((void**)&inlogBase, g_inlog);
    cudaGetSymbolAddress((void**)&pp, g_pp);
    float* inlog[2] = { inlogBase, inlogBase + (size_t)MAXN * K };

    const int TB = 256;
    int gE  = (E + TB - 1) / TB;
    int gE2 = (E2 + TB - 1) / TB;
    int n4  = (N * K) / 4;
    int gN4 = (n4 + TB - 1) / TB;
    int gN  = (N + TB - 1) / TB;

    // Launch order chosen so ncu (-s 5 -c 1) captures the steady-state k_update:
    // 0:k_zero_psi  1:k_scatter  2:pp  3:upd(it0)  4:pp  5:upd(it1) <- captured
    k_zero_psi<<<gN4, TB>>>(inlog[0], n4, potential);
    k_scatter<<<gE, TB>>>(messages, dst, inlog[0], E);

    for (int it = 0; it < ITERS; it++) {
        k_pp_zero<<<gN4, TB>>>(inlog[it & 1], prior, pp, inlog[(it + 1) & 1], n4);
        const float* cur = (it == 0) ? messages : msg;   // iter0 reads input, writes msg
        k_update<<<gE2, TB>>>(cur, msg, pp, src, dst, rev,
                              inlog[(it + 1) & 1], E2);
    }

    k_belief<<<gN, TB>>>(inlog[ITERS & 1], prior, out, N);
}